// round 9
// baseline (speedup 1.0000x reference)
#include <cuda_runtime.h>
#include <cuda_bf16.h>
#include <math.h>
#include <stdint.h>

#define D_MODEL 1024
#define BATCH   4
#define SEQ     4096

// ---------------------------------------------------------------------------
// Scratch (__device__ globals: allocation-free rule)
// ---------------------------------------------------------------------------
__device__ __align__(256) float g_S[(size_t)BATCH * SEQ * SEQ];                      // 256 MB

__device__ __align__(256) __nv_bfloat16 g_xh  [(size_t)BATCH * SEQ * D_MODEL];
__device__ __align__(256) __nv_bfloat16 g_xl  [(size_t)BATCH * SEQ * D_MODEL];
__device__ __align__(256) __nv_bfloat16 g_xth [(size_t)BATCH * D_MODEL * SEQ];       // x^T per batch
__device__ __align__(256) __nv_bfloat16 g_xtl [(size_t)BATCH * D_MODEL * SEQ];
__device__ __align__(256) __nv_bfloat16 g_QKth[(size_t)D_MODEL * D_MODEL];
__device__ __align__(256) __nv_bfloat16 g_QKtl[(size_t)D_MODEL * D_MODEL];
__device__ __align__(256) __nv_bfloat16 g_VOth[(size_t)D_MODEL * D_MODEL];
__device__ __align__(256) __nv_bfloat16 g_VOtl[(size_t)D_MODEL * D_MODEL];
__device__ __align__(256) __nv_bfloat16 g_xqkh[(size_t)BATCH * SEQ * D_MODEL];
__device__ __align__(256) __nv_bfloat16 g_xqkl[(size_t)BATCH * SEQ * D_MODEL];
__device__ __align__(256) __nv_bfloat16 g_Ph  [(size_t)BATCH * SEQ * SEQ];           // 128 MB
__device__ __align__(256) __nv_bfloat16 g_Pl  [(size_t)BATCH * SEQ * SEQ];           // 128 MB
__device__ __align__(256) __nv_bfloat16 g_avh [(size_t)BATCH * SEQ * D_MODEL];
__device__ __align__(256) __nv_bfloat16 g_avl [(size_t)BATCH * SEQ * D_MODEL];

// ---------------------------------------------------------------------------
// Helpers
// ---------------------------------------------------------------------------
__device__ __forceinline__ uint32_t smem_u32(const void* p) {
    uint32_t a;
    asm("{ .reg .u64 t; cvta.to.shared.u64 t, %1; cvt.u32.u64 %0, t; }" : "=r"(a) : "l"(p));
    return a;
}
__device__ __forceinline__ void cp16(uint32_t dst, const void* src) {
    asm volatile("cp.async.cg.shared.global [%0], [%1], 16;"
        :: "r"(dst), "l"(__cvta_generic_to_global(src)) : "memory");
}
#define CP_COMMIT() asm volatile("cp.async.commit_group;" ::: "memory")

__device__ __forceinline__ void ldsm_x4(uint32_t addr, uint32_t& r0, uint32_t& r1,
                                        uint32_t& r2, uint32_t& r3) {
    asm volatile("ldmatrix.sync.aligned.m8n8.x4.shared.b16 {%0,%1,%2,%3}, [%4];"
        : "=r"(r0), "=r"(r1), "=r"(r2), "=r"(r3) : "r"(addr));
}
__device__ __forceinline__ void mma_bf16(float* d, const uint32_t* a, uint32_t b0, uint32_t b1) {
    asm volatile(
        "mma.sync.aligned.m16n8k16.row.col.f32.bf16.bf16.f32 "
        "{%0,%1,%2,%3}, {%4,%5,%6,%7}, {%8,%9}, {%0,%1,%2,%3};"
        : "+f"(d[0]), "+f"(d[1]), "+f"(d[2]), "+f"(d[3])
        : "r"(a[0]), "r"(a[1]), "r"(a[2]), "r"(a[3]), "r"(b0), "r"(b1));
}
__device__ __forceinline__ void split2(float v, __nv_bfloat16& h, __nv_bfloat16& l) {
    h = __float2bfloat16(v);
    l = __float2bfloat16(v - __bfloat162float(h));
}

// ---------------------------------------------------------------------------
// Conversion kernels
// ---------------------------------------------------------------------------
__global__ __launch_bounds__(256)
void split_kernel(const float* __restrict__ in, __nv_bfloat16* __restrict__ hi,
                  __nv_bfloat16* __restrict__ lo, size_t n)
{
    size_t i = ((size_t)blockIdx.x * 256 + threadIdx.x) * 4;
    if (i >= n) return;
    float4 v = *reinterpret_cast<const float4*>(in + i);
    __nv_bfloat16 h0, h1, h2, h3, l0, l1, l2, l3;
    split2(v.x, h0, l0); split2(v.y, h1, l1); split2(v.z, h2, l2); split2(v.w, h3, l3);
    *reinterpret_cast<__nv_bfloat162*>(hi + i)     = __nv_bfloat162(h0, h1);
    *reinterpret_cast<__nv_bfloat162*>(hi + i + 2) = __nv_bfloat162(h2, h3);
    *reinterpret_cast<__nv_bfloat162*>(lo + i)     = __nv_bfloat162(l0, l1);
    *reinterpret_cast<__nv_bfloat162*>(lo + i + 2) = __nv_bfloat162(l2, l3);
}

// Transposed split: out[c][r] = in[r][c], per batch z. in: [R,C], out planes: [C,R].
__global__ __launch_bounds__(256)
void transpose_split_kernel(const float* __restrict__ in, __nv_bfloat16* __restrict__ hi,
                            __nv_bfloat16* __restrict__ lo, int R, int C)
{
    __shared__ float t[32][33];
    const size_t zoff = (size_t)blockIdx.z * R * C;
    const float* ib = in + zoff;
    const int r0 = blockIdx.y * 32, c0 = blockIdx.x * 32;
    const int tx = threadIdx.x, ty = threadIdx.y;   // 32 x 8
#pragma unroll
    for (int i = 0; i < 32; i += 8)
        t[ty + i][tx] = ib[(size_t)(r0 + ty + i) * C + c0 + tx];
    __syncthreads();
#pragma unroll
    for (int i = 0; i < 32; i += 8) {
        float v = t[tx][ty + i];
        size_t o = zoff + (size_t)(c0 + ty + i) * R + r0 + tx;
        __nv_bfloat16 h, l;
        split2(v, h, l);
        hi[o] = h;
        lo[o] = l;
    }
}

// ---------------------------------------------------------------------------
// mma.sync split-bf16 NT GEMM, MERGED passes:
//   D[m][n] = alpha * sum_k (Ah+Al)[m][k]*(Bh+Bl)[n][k]  (dropping Al*Bl)
//   Single K-loop; each iteration loads Ah/Al/Bh/Bl 128x64 tiles once and
//   issues all 3 MMA terms against them. fp32 accumulate in registers.
//   BM=BN=128, BK=64 (128B rows, SW128 XOR swizzle), 2-stage cp.async pipeline
//   (64KB/stage, 128KB total).
//   8 warps = 4(m) x 2(n); warp tile 32x64; atoms m16n8k16.
//   EPI=0: fp32 out.  EPI=1: hi/lo bf16 planes out.
// ---------------------------------------------------------------------------
#define GBM 128
#define GBN 128
#define GBK 64
#define NSTAGE 2
#define TILE_BYTES 16384                       // one 128x64 bf16 plane tile
#define STAGE_BYTES (4 * TILE_BYTES)           // Ah, Al, Bh, Bl
#define GEMM_SMEM (NSTAGE * STAGE_BYTES)       // 131072

template <int EPI>
__global__ __launch_bounds__(256)
void gemm_nt_mma(int M, int N, int K, float alpha,
                 const __nv_bfloat16* __restrict__ Ah, const __nv_bfloat16* __restrict__ Al, size_t sA,
                 const __nv_bfloat16* __restrict__ Bh, const __nv_bfloat16* __restrict__ Bl, size_t sB,
                 float* __restrict__ Cf, __nv_bfloat16* __restrict__ Ch, __nv_bfloat16* __restrict__ Cl,
                 size_t sC)
{
    extern __shared__ __align__(128) char sm[];
    const uint32_t smbase = smem_u32(sm);

    const int tid = threadIdx.x, lane = tid & 31, wid = tid >> 5;
    const int wm = wid & 3, wn = wid >> 2;            // 4 x 2 warp grid
    const int bm = blockIdx.y * GBM, bn = blockIdx.x * GBN;
    const size_t z = blockIdx.z;

    const int NIT = K / GBK;                          // 16 or 64 here; >= NSTAGE

    auto issue = [&](int it, int buf) {
        const __nv_bfloat16* srcs[4] = {
            Ah + z * sA + (size_t)bm * K + it * GBK,
            Al + z * sA + (size_t)bm * K + it * GBK,
            Bh + z * sB + (size_t)bn * K + it * GBK,
            Bl + z * sB + (size_t)bn * K + it * GBK
        };
        const uint32_t sb = smbase + buf * STAGE_BYTES;
#pragma unroll
        for (int p = 0; p < 4; p++) {
            const uint32_t dst = sb + p * TILE_BYTES;
            const __nv_bfloat16* src = srcs[p];
#pragma unroll
            for (int i = 0; i < 4; i++) {
                int c   = tid + i * 256;
                int row = c >> 3;            // 0..127
                int ck  = c & 7;             // 16B chunk within 128B row
                uint32_t off = (uint32_t)(row * 128 + ((ck * 16) ^ ((row & 7) << 4)));
                cp16(dst + off, src + (size_t)row * K + ck * 8);
            }
        }
        CP_COMMIT();
    };

    float d[2][8][4];
#pragma unroll
    for (int am = 0; am < 2; am++)
#pragma unroll
        for (int an = 0; an < 8; an++)
#pragma unroll
            for (int q = 0; q < 4; q++) d[am][an][q] = 0.0f;

    issue(0, 0);
    issue(1, 1);

    const int lrow = lane & 15;
    const int lcol = (lane >> 4) * 16;   // byte offset of 8-half group

    for (int it = 0; it < NIT; it++) {
        // Retire the group that fills buffer `it & 1` (tail-aware wait count).
        if (it + 1 < NIT) asm volatile("cp.async.wait_group 1;" ::: "memory");
        else              asm volatile("cp.async.wait_group 0;" ::: "memory");
        __syncthreads();

        const int buf = it & 1;
        const uint32_t sb  = smbase + buf * STAGE_BYTES;
        const uint32_t AaH = sb;
        const uint32_t AaL = sb + TILE_BYTES;
        const uint32_t BaH = sb + 2 * TILE_BYTES;
        const uint32_t BaL = sb + 3 * TILE_BYTES;

#pragma unroll
        for (int kk = 0; kk < 4; kk++) {
            const int colb = kk * 32 + lcol;
            uint32_t ah[2][4], al[2][4], b[4][4];
            // A fragments, both planes
#pragma unroll
            for (int am = 0; am < 2; am++) {
                int row = wm * 32 + am * 16 + lrow;
                uint32_t off = (uint32_t)(row * 128 + (colb ^ ((row & 7) << 4)));
                ldsm_x4(AaH + off, ah[am][0], ah[am][1], ah[am][2], ah[am][3]);
                ldsm_x4(AaL + off, al[am][0], al[am][1], al[am][2], al[am][3]);
            }
            // B hi plane -> Ah*Bh and Al*Bh
#pragma unroll
            for (int nb = 0; nb < 4; nb++) {
                int row = wn * 64 + nb * 16 + lrow;
                uint32_t off = (uint32_t)(row * 128 + (colb ^ ((row & 7) << 4)));
                ldsm_x4(BaH + off, b[nb][0], b[nb][1], b[nb][2], b[nb][3]);
            }
#pragma unroll
            for (int am = 0; am < 2; am++)
#pragma unroll
                for (int an = 0; an < 8; an++) {
                    mma_bf16(d[am][an], ah[am], b[an >> 1][an & 1], b[an >> 1][(an & 1) + 2]);
                    mma_bf16(d[am][an], al[am], b[an >> 1][an & 1], b[an >> 1][(an & 1) + 2]);
                }
            // B lo plane -> Ah*Bl (reuse b registers)
#pragma unroll
            for (int nb = 0; nb < 4; nb++) {
                int row = wn * 64 + nb * 16 + lrow;
                uint32_t off = (uint32_t)(row * 128 + (colb ^ ((row & 7) << 4)));
                ldsm_x4(BaL + off, b[nb][0], b[nb][1], b[nb][2], b[nb][3]);
            }
#pragma unroll
            for (int am = 0; am < 2; am++)
#pragma unroll
                for (int an = 0; an < 8; an++)
                    mma_bf16(d[am][an], ah[am], b[an >> 1][an & 1], b[an >> 1][(an & 1) + 2]);
        }
        __syncthreads();
        if (it + NSTAGE < NIT) issue(it + NSTAGE, buf);
    }

    // Epilogue: per-atom store. c0,c1 at (row, col..col+1); c2,c3 at (row+8, ...).
    const int er = lane >> 2;
    const int ec = (lane & 3) * 2;
#pragma unroll
    for (int am = 0; am < 2; am++) {
#pragma unroll
        for (int an = 0; an < 8; an++) {
            const int row = bm + wm * 32 + am * 16 + er;
            const int col = bn + wn * 64 + an * 8 + ec;
            const float v0 = d[am][an][0] * alpha;
            const float v1 = d[am][an][1] * alpha;
            const float v2 = d[am][an][2] * alpha;
            const float v3 = d[am][an][3] * alpha;
            const size_t o0 = z * sC + (size_t)row * N + col;
            const size_t o1 = z * sC + (size_t)(row + 8) * N + col;
            if (EPI == 0) {
                *reinterpret_cast<float2*>(Cf + o0) = make_float2(v0, v1);
                *reinterpret_cast<float2*>(Cf + o1) = make_float2(v2, v3);
            } else {
                __nv_bfloat16 h0, l0, h1, l1;
                split2(v0, h0, l0); split2(v1, h1, l1);
                *reinterpret_cast<__nv_bfloat162*>(Ch + o0) = __nv_bfloat162(h0, h1);
                *reinterpret_cast<__nv_bfloat162*>(Cl + o0) = __nv_bfloat162(l0, l1);
                split2(v2, h0, l0); split2(v3, h1, l1);
                *reinterpret_cast<__nv_bfloat162*>(Ch + o1) = __nv_bfloat162(h0, h1);
                *reinterpret_cast<__nv_bfloat162*>(Cl + o1) = __nv_bfloat162(l0, l1);
            }
        }
    }
}

// ---------------------------------------------------------------------------
// Row softmax over SEQ=4096: reads fp32 S, writes split bf16 P (hi/lo planes)
// ---------------------------------------------------------------------------
__global__ __launch_bounds__(256)
void softmax_split_kernel(const float* __restrict__ S,
                          __nv_bfloat16* __restrict__ Ph, __nv_bfloat16* __restrict__ Pl)
{
    __shared__ float red[8];
    const size_t row = blockIdx.x;
    const float* p = S + row * (size_t)SEQ;
    const int tid = threadIdx.x, lane = tid & 31, warp = tid >> 5;

    float4 v[4];
    float m = -INFINITY;
#pragma unroll
    for (int i = 0; i < 4; i++) {
        v[i] = *reinterpret_cast<const float4*>(p + (size_t)(i * 256 + tid) * 4);
        m = fmaxf(m, fmaxf(fmaxf(v[i].x, v[i].y), fmaxf(v[i].z, v[i].w)));
    }
#pragma unroll
    for (int o = 16; o > 0; o >>= 1) m = fmaxf(m, __shfl_xor_sync(0xffffffffu, m, o));
    if (lane == 0) red[warp] = m;
    __syncthreads();
    if (warp == 0) {
        float t = red[lane & 7];
#pragma unroll
        for (int o = 4; o > 0; o >>= 1) t = fmaxf(t, __shfl_xor_sync(0xffffffffu, t, o));
        if (lane == 0) red[0] = t;
    }
    __syncthreads();
    m = red[0];
    __syncthreads();

    float s = 0.0f;
#pragma unroll
    for (int i = 0; i < 4; i++) {
        v[i].x = __expf(v[i].x - m);
        v[i].y = __expf(v[i].y - m);
        v[i].z = __expf(v[i].z - m);
        v[i].w = __expf(v[i].w - m);
        s += (v[i].x + v[i].y) + (v[i].z + v[i].w);
    }
#pragma unroll
    for (int o = 16; o > 0; o >>= 1) s += __shfl_xor_sync(0xffffffffu, s, o);
    if (lane == 0) red[warp] = s;
    __syncthreads();
    if (warp == 0) {
        float t = red[lane & 7];
#pragma unroll
        for (int o = 4; o > 0; o >>= 1) t += __shfl_xor_sync(0xffffffffu, t, o);
        if (lane == 0) red[0] = t;
    }
    __syncthreads();
    const float inv = 1.0f / red[0];

    const size_t rb = row * (size_t)SEQ;
#pragma unroll
    for (int i = 0; i < 4; i++) {
        size_t idx = rb + (size_t)(i * 256 + tid) * 4;
        __nv_bfloat16 h0, h1, h2, h3, l0, l1, l2, l3;
        split2(v[i].x * inv, h0, l0);
        split2(v[i].y * inv, h1, l1);
        split2(v[i].z * inv, h2, l2);
        split2(v[i].w * inv, h3, l3);
        *reinterpret_cast<__nv_bfloat162*>(Ph + idx)     = __nv_bfloat162(h0, h1);
        *reinterpret_cast<__nv_bfloat162*>(Ph + idx + 2) = __nv_bfloat162(h2, h3);
        *reinterpret_cast<__nv_bfloat162*>(Pl + idx)     = __nv_bfloat162(l0, l1);
        *reinterpret_cast<__nv_bfloat162*>(Pl + idx + 2) = __nv_bfloat162(l2, l3);
    }
}

// ---------------------------------------------------------------------------
extern "C" void kernel_launch(void* const* d_in, const int* in_sizes, int n_in,
                              void* d_out, int out_size)
{
    const float* x  = (const float*)d_in[0];   // [B, T, D]
    const float* QK = (const float*)d_in[1];   // [D, D]
    const float* VO = (const float*)d_in[2];   // [D, D]
    float* out = (float*)d_out;                // [B, T, D]

    float* S;
    __nv_bfloat16 *xh, *xl, *xth, *xtl, *qkh, *qkl, *voh, *vol;
    __nv_bfloat16 *xqkh, *xqkl, *Ph, *Pl, *avh, *avl;
    cudaGetSymbolAddress((void**)&S,    g_S);
    cudaGetSymbolAddress((void**)&xh,   g_xh);
    cudaGetSymbolAddress((void**)&xl,   g_xl);
    cudaGetSymbolAddress((void**)&xth,  g_xth);
    cudaGetSymbolAddress((void**)&xtl,  g_xtl);
    cudaGetSymbolAddress((void**)&qkh,  g_QKth);
    cudaGetSymbolAddress((void**)&qkl,  g_QKtl);
    cudaGetSymbolAddress((void**)&voh,  g_VOth);
    cudaGetSymbolAddress((void**)&vol,  g_VOtl);
    cudaGetSymbolAddress((void**)&xqkh, g_xqkh);
    cudaGetSymbolAddress((void**)&xqkl, g_xqkl);
    cudaGetSymbolAddress((void**)&Ph,   g_Ph);
    cudaGetSymbolAddress((void**)&Pl,   g_Pl);
    cudaGetSymbolAddress((void**)&avh,  g_avh);
    cudaGetSymbolAddress((void**)&avl,  g_avl);

    cudaFuncSetAttribute(gemm_nt_mma<0>, cudaFuncAttributeMaxDynamicSharedMemorySize, GEMM_SMEM);
    cudaFuncSetAttribute(gemm_nt_mma<1>, cudaFuncAttributeMaxDynamicSharedMemorySize, GEMM_SMEM);

    const size_t nx = (size_t)BATCH * SEQ * D_MODEL;   // 16M
    const size_t TD = (size_t)SEQ * D_MODEL;
    const size_t DT = (size_t)D_MODEL * SEQ;
    const size_t TT = (size_t)SEQ * SEQ;
    const float scale = 1.0f / 32.0f;                  // 1/sqrt(1024)

    // ---- conversions ----
    split_kernel<<<(unsigned)(nx / 1024), 256>>>(x, xh, xl, nx);
    transpose_split_kernel<<<dim3(D_MODEL / 32, D_MODEL / 32, 1), dim3(32, 8)>>>(QK, qkh, qkl, D_MODEL, D_MODEL);
    transpose_split_kernel<<<dim3(D_MODEL / 32, D_MODEL / 32, 1), dim3(32, 8)>>>(VO, voh, vol, D_MODEL, D_MODEL);
    transpose_split_kernel<<<dim3(D_MODEL / 32, SEQ / 32, BATCH), dim3(32, 8)>>>(x, xth, xtl, SEQ, D_MODEL);

    // ---- 1) xQK = x @ QK : NT vs QK^T -> split planes
    gemm_nt_mma<1><<<dim3(D_MODEL / GBN, (BATCH * SEQ) / GBM, 1), 256, GEMM_SMEM>>>(
        BATCH * SEQ, D_MODEL, D_MODEL, 1.0f,
        xh, xl, 0, qkh, qkl, 0, nullptr, xqkh, xqkl, 0);

    // ---- 2) S = (xQK @ x^T)/32 : NT per batch -> fp32
    gemm_nt_mma<0><<<dim3(SEQ / GBN, SEQ / GBM, BATCH), 256, GEMM_SMEM>>>(
        SEQ, SEQ, D_MODEL, scale,
        xqkh, xqkl, TD, xh, xl, TD, S, nullptr, nullptr, TT);

    // ---- 3) P = softmax(S) -> split planes
    softmax_split_kernel<<<BATCH * SEQ, 256>>>(S, Ph, Pl);

    // ---- 4) av = P @ x : NT vs x^T per batch -> split planes
    gemm_nt_mma<1><<<dim3(D_MODEL / GBN, SEQ / GBM, BATCH), 256, GEMM_SMEM>>>(
        SEQ, D_MODEL, SEQ, 1.0f,
        Ph, Pl, TT, xth, xtl, DT, nullptr, avh, avl, TD);

    // ---- 5) out = av @ VO : NT vs VO^T -> fp32
    gemm_nt_mma<0><<<dim3(D_MODEL / GBN, (BATCH * SEQ) / GBM, 1), 256, GEMM_SMEM>>>(
        BATCH * SEQ, D_MODEL, D_MODEL, 1.0f,
        avh, avl, 0, voh, vol, 0, out, nullptr, nullptr, TD);
}

// round 10
// speedup vs baseline: 1.5883x; 1.5883x over previous
#include <cuda_runtime.h>
#include <cuda_fp16.h>
#include <math.h>
#include <stdint.h>

#define D_MODEL 1024
#define BATCH   4
#define SEQ     4096

// ---------------------------------------------------------------------------
// Scratch (__device__ globals: allocation-free rule)
// ---------------------------------------------------------------------------
__device__ __align__(256) float g_S[(size_t)BATCH * SEQ * SEQ];                 // 256 MB

__device__ __align__(256) __half g_xh  [(size_t)BATCH * SEQ * D_MODEL];         // x fp16 (single plane)
__device__ __align__(256) __half g_xth [(size_t)BATCH * D_MODEL * SEQ];         // x^T hi
__device__ __align__(256) __half g_xtl [(size_t)BATCH * D_MODEL * SEQ];         // x^T lo
__device__ __align__(256) __half g_QKth[(size_t)D_MODEL * D_MODEL];             // QK^T hi
__device__ __align__(256) __half g_QKtl[(size_t)D_MODEL * D_MODEL];             // QK^T lo
__device__ __align__(256) __half g_VOth[(size_t)D_MODEL * D_MODEL];             // VO^T (single plane)
__device__ __align__(256) __half g_xqkh[(size_t)BATCH * SEQ * D_MODEL];
__device__ __align__(256) __half g_xqkl[(size_t)BATCH * SEQ * D_MODEL];
__device__ __align__(256) __half g_Ph  [(size_t)BATCH * SEQ * SEQ];             // 128 MB (single plane)
__device__ __align__(256) __half g_avh [(size_t)BATCH * SEQ * D_MODEL];
__device__ __align__(256) __half g_avl [(size_t)BATCH * SEQ * D_MODEL];

// ---------------------------------------------------------------------------
// Helpers
// ---------------------------------------------------------------------------
__device__ __forceinline__ uint32_t smem_u32(const void* p) {
    uint32_t a;
    asm("{ .reg .u64 t; cvta.to.shared.u64 t, %1; cvt.u32.u64 %0, t; }" : "=r"(a) : "l"(p));
    return a;
}
__device__ __forceinline__ void cp16(uint32_t dst, const void* src) {
    asm volatile("cp.async.cg.shared.global [%0], [%1], 16;"
        :: "r"(dst), "l"(__cvta_generic_to_global(src)) : "memory");
}
#define CP_COMMIT() asm volatile("cp.async.commit_group;" ::: "memory")

__device__ __forceinline__ void ldsm_x4(uint32_t addr, uint32_t& r0, uint32_t& r1,
                                        uint32_t& r2, uint32_t& r3) {
    asm volatile("ldmatrix.sync.aligned.m8n8.x4.shared.b16 {%0,%1,%2,%3}, [%4];"
        : "=r"(r0), "=r"(r1), "=r"(r2), "=r"(r3) : "r"(addr));
}
__device__ __forceinline__ void mma_fp16(float* d, const uint32_t* a, uint32_t b0, uint32_t b1) {
    asm volatile(
        "mma.sync.aligned.m16n8k16.row.col.f32.f16.f16.f32 "
        "{%0,%1,%2,%3}, {%4,%5,%6,%7}, {%8,%9}, {%0,%1,%2,%3};"
        : "+f"(d[0]), "+f"(d[1]), "+f"(d[2]), "+f"(d[3])
        : "r"(a[0]), "r"(a[1]), "r"(a[2]), "r"(a[3]), "r"(b0), "r"(b1));
}
__device__ __forceinline__ void split2h(float v, __half& h, __half& l) {
    h = __float2half_rn(v);
    l = __float2half_rn(v - __half2float(h));
}

// ---------------------------------------------------------------------------
// Conversion kernels
// ---------------------------------------------------------------------------
__global__ __launch_bounds__(256)
void tohalf_kernel(const float* __restrict__ in, __half* __restrict__ out, size_t n)
{
    size_t i = ((size_t)blockIdx.x * 256 + threadIdx.x) * 4;
    if (i >= n) return;
    float4 v = *reinterpret_cast<const float4*>(in + i);
    *reinterpret_cast<__half2*>(out + i)     = __floats2half2_rn(v.x, v.y);
    *reinterpret_cast<__half2*>(out + i + 2) = __floats2half2_rn(v.z, v.w);
}

// Transposed split: out[c][r] = in[r][c], per batch z. in: [R,C], hi/lo: [C,R].
__global__ __launch_bounds__(256)
void transpose_split_h(const float* __restrict__ in, __half* __restrict__ hi,
                       __half* __restrict__ lo, int R, int C)
{
    __shared__ float t[32][33];
    const size_t zoff = (size_t)blockIdx.z * R * C;
    const float* ib = in + zoff;
    const int r0 = blockIdx.y * 32, c0 = blockIdx.x * 32;
    const int tx = threadIdx.x, ty = threadIdx.y;   // 32 x 8
#pragma unroll
    for (int i = 0; i < 32; i += 8)
        t[ty + i][tx] = ib[(size_t)(r0 + ty + i) * C + c0 + tx];
    __syncthreads();
#pragma unroll
    for (int i = 0; i < 32; i += 8) {
        float v = t[tx][ty + i];
        size_t o = zoff + (size_t)(c0 + ty + i) * R + r0 + tx;
        __half h, l;
        split2h(v, h, l);
        hi[o] = h;
        lo[o] = l;
    }
}

// Transposed single-plane convert.
__global__ __launch_bounds__(256)
void transpose_h(const float* __restrict__ in, __half* __restrict__ hi, int R, int C)
{
    __shared__ float t[32][33];
    const size_t zoff = (size_t)blockIdx.z * R * C;
    const float* ib = in + zoff;
    const int r0 = blockIdx.y * 32, c0 = blockIdx.x * 32;
    const int tx = threadIdx.x, ty = threadIdx.y;
#pragma unroll
    for (int i = 0; i < 32; i += 8)
        t[ty + i][tx] = ib[(size_t)(r0 + ty + i) * C + c0 + tx];
    __syncthreads();
#pragma unroll
    for (int i = 0; i < 32; i += 8) {
        size_t o = zoff + (size_t)(c0 + ty + i) * R + r0 + tx;
        hi[o] = __float2half_rn(t[tx][ty + i]);
    }
}

// ---------------------------------------------------------------------------
// mma.sync fp16 asymmetric-split NT GEMM (2 MMA terms):
//   SPLIT_A=1: D = alpha * (A0 + A1) . B0^T      (A 22-bit, B0 11-bit)
//   SPLIT_A=0: D = alpha * A0 . (B0 + B1)^T      (A 11-bit, B 22-bit)
//   fp32 accumulate in registers. BM=BN=128, BK=64 (128B rows, XOR swizzle),
//   2-stage cp.async, 3 planes/stage (48KB; 96KB total -> 2 CTAs/SM).
//   8 warps = 4(m) x 2(n); warp tile 32x64; atoms m16n8k16.
//   EPI=0: fp32 out.  EPI=1: hi/lo fp16 planes out.
// ---------------------------------------------------------------------------
#define GBM 128
#define GBN 128
#define GBK 64
#define NSTAGE 2
#define TILE_BYTES 16384                       // one 128x64 fp16 plane tile
#define STAGE_BYTES (3 * TILE_BYTES)           // [A0][AX/BX][B0]
#define GEMM_SMEM (NSTAGE * STAGE_BYTES)       // 98304

template <int EPI, int SPLIT_A>
__global__ __launch_bounds__(256)
void gemm_nt_mma(int M, int N, int K, float alpha,
                 const __half* __restrict__ A0, const __half* __restrict__ AX, size_t sA,
                 const __half* __restrict__ B0, size_t sB,
                 float* __restrict__ Cf, __half* __restrict__ Ch, __half* __restrict__ Cl,
                 size_t sC)
{
    extern __shared__ __align__(128) char sm[];
    const uint32_t smbase = smem_u32(sm);

    const int tid = threadIdx.x, lane = tid & 31, wid = tid >> 5;
    const int wm = wid & 3, wn = wid >> 2;            // 4 x 2 warp grid
    const int bm = blockIdx.y * GBM, bn = blockIdx.x * GBN;
    const size_t z = blockIdx.z;

    const int NIT = K / GBK;

    auto issue = [&](int it, int buf) {
        const __half* srcs[3];
        srcs[0] = A0 + z * sA + (size_t)bm * K + it * GBK;
        srcs[1] = SPLIT_A ? (AX + z * sA + (size_t)bm * K + it * GBK)
                          : (AX + z * sB + (size_t)bn * K + it * GBK);
        srcs[2] = B0 + z * sB + (size_t)bn * K + it * GBK;
        const uint32_t sb = smbase + buf * STAGE_BYTES;
#pragma unroll
        for (int p = 0; p < 3; p++) {
            const uint32_t dst = sb + p * TILE_BYTES;
            const __half* src = srcs[p];
#pragma unroll
            for (int i = 0; i < 4; i++) {
                int c   = tid + i * 256;
                int row = c >> 3;            // 0..127
                int ck  = c & 7;             // 16B chunk within 128B row
                uint32_t off = (uint32_t)(row * 128 + ((ck * 16) ^ ((row & 7) << 4)));
                cp16(dst + off, src + (size_t)row * K + ck * 8);
            }
        }
        CP_COMMIT();
    };

    float d[2][8][4];
#pragma unroll
    for (int am = 0; am < 2; am++)
#pragma unroll
        for (int an = 0; an < 8; an++)
#pragma unroll
            for (int q = 0; q < 4; q++) d[am][an][q] = 0.0f;

    issue(0, 0);
    issue(1, 1);

    const int lrow = lane & 15;
    const int lcol = (lane >> 4) * 16;   // byte offset of 8-half group

    for (int it = 0; it < NIT; it++) {
        if (it + 1 < NIT) asm volatile("cp.async.wait_group 1;" ::: "memory");
        else              asm volatile("cp.async.wait_group 0;" ::: "memory");
        __syncthreads();

        const int buf = it & 1;
        const uint32_t sb = smbase + buf * STAGE_BYTES;
        const uint32_t T0 = sb;                   // A0
        const uint32_t T1 = sb + TILE_BYTES;      // A1 (SPLIT_A) or B1
        const uint32_t T2 = sb + 2 * TILE_BYTES;  // B0

#pragma unroll
        for (int kk = 0; kk < 4; kk++) {
            const int colb = kk * 32 + lcol;
            uint32_t a0[2][4], ax[2][4], b[4][4];
#pragma unroll
            for (int am = 0; am < 2; am++) {
                int row = wm * 32 + am * 16 + lrow;
                uint32_t off = (uint32_t)(row * 128 + (colb ^ ((row & 7) << 4)));
                ldsm_x4(T0 + off, a0[am][0], a0[am][1], a0[am][2], a0[am][3]);
                if (SPLIT_A)
                    ldsm_x4(T1 + off, ax[am][0], ax[am][1], ax[am][2], ax[am][3]);
            }
#pragma unroll
            for (int nb = 0; nb < 4; nb++) {
                int row = wn * 64 + nb * 16 + lrow;
                uint32_t off = (uint32_t)(row * 128 + (colb ^ ((row & 7) << 4)));
                ldsm_x4(T2 + off, b[nb][0], b[nb][1], b[nb][2], b[nb][3]);
            }
            // Term 1: A0 . B0
#pragma unroll
            for (int am = 0; am < 2; am++)
#pragma unroll
                for (int an = 0; an < 8; an++)
                    mma_fp16(d[am][an], a0[am], b[an >> 1][an & 1], b[an >> 1][(an & 1) + 2]);
            if (SPLIT_A) {
                // Term 2: A1 . B0  (b regs reused)
#pragma unroll
                for (int am = 0; am < 2; am++)
#pragma unroll
                    for (int an = 0; an < 8; an++)
                        mma_fp16(d[am][an], ax[am], b[an >> 1][an & 1], b[an >> 1][(an & 1) + 2]);
            } else {
                // Term 2: A0 . B1  (reload b regs from T1)
#pragma unroll
                for (int nb = 0; nb < 4; nb++) {
                    int row = wn * 64 + nb * 16 + lrow;
                    uint32_t off = (uint32_t)(row * 128 + (colb ^ ((row & 7) << 4)));
                    ldsm_x4(T1 + off, b[nb][0], b[nb][1], b[nb][2], b[nb][3]);
                }
#pragma unroll
                for (int am = 0; am < 2; am++)
#pragma unroll
                    for (int an = 0; an < 8; an++)
                        mma_fp16(d[am][an], a0[am], b[an >> 1][an & 1], b[an >> 1][(an & 1) + 2]);
            }
        }
        __syncthreads();
        if (it + NSTAGE < NIT) issue(it + NSTAGE, buf);
    }

    // Epilogue: per-atom store. c0,c1 at (row, col..col+1); c2,c3 at (row+8, ...).
    const int er = lane >> 2;
    const int ec = (lane & 3) * 2;
#pragma unroll
    for (int am = 0; am < 2; am++) {
#pragma unroll
        for (int an = 0; an < 8; an++) {
            const int row = bm + wm * 32 + am * 16 + er;
            const int col = bn + wn * 64 + an * 8 + ec;
            const float v0 = d[am][an][0] * alpha;
            const float v1 = d[am][an][1] * alpha;
            const float v2 = d[am][an][2] * alpha;
            const float v3 = d[am][an][3] * alpha;
            const size_t o0 = z * sC + (size_t)row * N + col;
            const size_t o1 = z * sC + (size_t)(row + 8) * N + col;
            if (EPI == 0) {
                *reinterpret_cast<float2*>(Cf + o0) = make_float2(v0, v1);
                *reinterpret_cast<float2*>(Cf + o1) = make_float2(v2, v3);
            } else {
                __half h0, l0, h1, l1;
                split2h(v0, h0, l0); split2h(v1, h1, l1);
                *reinterpret_cast<__half2*>(Ch + o0) = __halves2half2(h0, h1);
                *reinterpret_cast<__half2*>(Cl + o0) = __halves2half2(l0, l1);
                split2h(v2, h0, l0); split2h(v3, h1, l1);
                *reinterpret_cast<__half2*>(Ch + o1) = __halves2half2(h0, h1);
                *reinterpret_cast<__half2*>(Cl + o1) = __halves2half2(l0, l1);
            }
        }
    }
}

// ---------------------------------------------------------------------------
// Row softmax over SEQ=4096: reads fp32 S, writes single fp16 plane P
// ---------------------------------------------------------------------------
__global__ __launch_bounds__(256)
void softmax_h_kernel(const float* __restrict__ S, __half* __restrict__ Ph)
{
    __shared__ float red[8];
    const size_t row = blockIdx.x;
    const float* p = S + row * (size_t)SEQ;
    const int tid = threadIdx.x, lane = tid & 31, warp = tid >> 5;

    float4 v[4];
    float m = -INFINITY;
#pragma unroll
    for (int i = 0; i < 4; i++) {
        v[i] = *reinterpret_cast<const float4*>(p + (size_t)(i * 256 + tid) * 4);
        m = fmaxf(m, fmaxf(fmaxf(v[i].x, v[i].y), fmaxf(v[i].z, v[i].w)));
    }
#pragma unroll
    for (int o = 16; o > 0; o >>= 1) m = fmaxf(m, __shfl_xor_sync(0xffffffffu, m, o));
    if (lane == 0) red[warp] = m;
    __syncthreads();
    if (warp == 0) {
        float t = red[lane & 7];
#pragma unroll
        for (int o = 4; o > 0; o >>= 1) t = fmaxf(t, __shfl_xor_sync(0xffffffffu, t, o));
        if (lane == 0) red[0] = t;
    }
    __syncthreads();
    m = red[0];
    __syncthreads();

    float s = 0.0f;
#pragma unroll
    for (int i = 0; i < 4; i++) {
        v[i].x = __expf(v[i].x - m);
        v[i].y = __expf(v[i].y - m);
        v[i].z = __expf(v[i].z - m);
        v[i].w = __expf(v[i].w - m);
        s += (v[i].x + v[i].y) + (v[i].z + v[i].w);
    }
#pragma unroll
    for (int o = 16; o > 0; o >>= 1) s += __shfl_xor_sync(0xffffffffu, s, o);
    if (lane == 0) red[warp] = s;
    __syncthreads();
    if (warp == 0) {
        float t = red[lane & 7];
#pragma unroll
        for (int o = 4; o > 0; o >>= 1) t += __shfl_xor_sync(0xffffffffu, t, o);
        if (lane == 0) red[0] = t;
    }
    __syncthreads();
    const float inv = 1.0f / red[0];

    const size_t rb = row * (size_t)SEQ;
#pragma unroll
    for (int i = 0; i < 4; i++) {
        size_t idx = rb + (size_t)(i * 256 + tid) * 4;
        *reinterpret_cast<__half2*>(Ph + idx)     = __floats2half2_rn(v[i].x * inv, v[i].y * inv);
        *reinterpret_cast<__half2*>(Ph + idx + 2) = __floats2half2_rn(v[i].z * inv, v[i].w * inv);
    }
}

// ---------------------------------------------------------------------------
extern "C" void kernel_launch(void* const* d_in, const int* in_sizes, int n_in,
                              void* d_out, int out_size)
{
    const float* x  = (const float*)d_in[0];   // [B, T, D]
    const float* QK = (const float*)d_in[1];   // [D, D]
    const float* VO = (const float*)d_in[2];   // [D, D]
    float* out = (float*)d_out;                // [B, T, D]

    float* S;
    __half *xh, *xth, *xtl, *qkth, *qktl, *voth;
    __half *xqkh, *xqkl, *Ph, *avh, *avl;
    cudaGetSymbolAddress((void**)&S,    g_S);
    cudaGetSymbolAddress((void**)&xh,   g_xh);
    cudaGetSymbolAddress((void**)&xth,  g_xth);
    cudaGetSymbolAddress((void**)&xtl,  g_xtl);
    cudaGetSymbolAddress((void**)&qkth, g_QKth);
    cudaGetSymbolAddress((void**)&qktl, g_QKtl);
    cudaGetSymbolAddress((void**)&voth, g_VOth);
    cudaGetSymbolAddress((void**)&xqkh, g_xqkh);
    cudaGetSymbolAddress((void**)&xqkl, g_xqkl);
    cudaGetSymbolAddress((void**)&Ph,   g_Ph);
    cudaGetSymbolAddress((void**)&avh,  g_avh);
    cudaGetSymbolAddress((void**)&avl,  g_avl);

    cudaFuncSetAttribute(gemm_nt_mma<0, 1>, cudaFuncAttributeMaxDynamicSharedMemorySize, GEMM_SMEM);
    cudaFuncSetAttribute(gemm_nt_mma<1, 0>, cudaFuncAttributeMaxDynamicSharedMemorySize, GEMM_SMEM);

    const size_t nx = (size_t)BATCH * SEQ * D_MODEL;   // 16M
    const size_t TD = (size_t)SEQ * D_MODEL;
    const size_t DT = (size_t)D_MODEL * SEQ;
    const size_t TT = (size_t)SEQ * SEQ;
    const float scale = 1.0f / 32.0f;                  // 1/sqrt(1024)

    // ---- conversions ----
    tohalf_kernel<<<(unsigned)(nx / 1024), 256>>>(x, xh, nx);
    transpose_split_h<<<dim3(D_MODEL / 32, D_MODEL / 32, 1), dim3(32, 8)>>>(QK, qkth, qktl, D_MODEL, D_MODEL);
    transpose_h<<<dim3(D_MODEL / 32, D_MODEL / 32, 1), dim3(32, 8)>>>(VO, voth, D_MODEL, D_MODEL);
    transpose_split_h<<<dim3(D_MODEL / 32, SEQ / 32, BATCH), dim3(32, 8)>>>(x, xth, xtl, SEQ, D_MODEL);

    // ---- 1) xQK = x . (QKh + QKl)^T : B-split -> fp16 planes
    gemm_nt_mma<1, 0><<<dim3(D_MODEL / GBN, (BATCH * SEQ) / GBM, 1), 256, GEMM_SMEM>>>(
        BATCH * SEQ, D_MODEL, D_MODEL, 1.0f,
        xh, qktl, 0, qkth, 0, nullptr, xqkh, xqkl, 0);

    // ---- 2) S = ((xqkh + xqkl) . x^T)/32 : A-split, per batch -> fp32
    gemm_nt_mma<0, 1><<<dim3(SEQ / GBN, SEQ / GBM, BATCH), 256, GEMM_SMEM>>>(
        SEQ, SEQ, D_MODEL, scale,
        xqkh, xqkl, TD, xh, TD, S, nullptr, nullptr, TT);

    // ---- 3) P = softmax(S) -> single fp16 plane
    softmax_h_kernel<<<BATCH * SEQ, 256>>>(S, Ph);

    // ---- 4) av = P . (xth + xtl)^T : B-split, per batch -> fp16 planes
    gemm_nt_mma<1, 0><<<dim3(D_MODEL / GBN, SEQ / GBM, BATCH), 256, GEMM_SMEM>>>(
        SEQ, D_MODEL, SEQ, 1.0f,
        Ph, xtl, TT, xth, DT, nullptr, avh, avl, TD);

    // ---- 5) out = (avh + avl) . VO^T : A-split -> fp32
    gemm_nt_mma<0, 1><<<dim3(D_MODEL / GBN, (BATCH * SEQ) / GBM, 1), 256, GEMM_SMEM>>>(
        BATCH * SEQ, D_MODEL, D_MODEL, 1.0f,
        avh, avl, 0, voth, 0, out, nullptr, nullptr, 0);
}

// round 11
// speedup vs baseline: 2.8193x; 1.7751x over previous
#include <cuda_runtime.h>
#include <cuda_fp16.h>
#include <math.h>
#include <stdint.h>

#define D_MODEL 1024
#define BATCH   4
#define SEQ     4096

// ---------------------------------------------------------------------------
// Scratch (__device__ globals: allocation-free rule)
// ---------------------------------------------------------------------------
__device__ __align__(256) float  g_S   [(size_t)BATCH * SEQ * SEQ];             // 256 MB
__device__ __align__(256) __half g_xh  [(size_t)BATCH * SEQ * D_MODEL];         // x fp16
__device__ __align__(256) __half g_xth [(size_t)BATCH * D_MODEL * SEQ];         // x^T fp16
__device__ __align__(256) __half g_QKt [(size_t)D_MODEL * D_MODEL];             // QK^T fp16
__device__ __align__(256) __half g_VOt [(size_t)D_MODEL * D_MODEL];             // VO^T fp16
__device__ __align__(256) __half g_xqk [(size_t)BATCH * SEQ * D_MODEL];
__device__ __align__(256) __half g_P   [(size_t)BATCH * SEQ * SEQ];             // 128 MB
__device__ __align__(256) __half g_av  [(size_t)BATCH * SEQ * D_MODEL];

// ---------------------------------------------------------------------------
// Helpers
// ---------------------------------------------------------------------------
__device__ __forceinline__ uint32_t smem_u32(const void* p) {
    uint32_t a;
    asm("{ .reg .u64 t; cvta.to.shared.u64 t, %1; cvt.u32.u64 %0, t; }" : "=r"(a) : "l"(p));
    return a;
}
__device__ __forceinline__ void cp16(uint32_t dst, const void* src) {
    asm volatile("cp.async.cg.shared.global [%0], [%1], 16;"
        :: "r"(dst), "l"(__cvta_generic_to_global(src)) : "memory");
}
#define CP_COMMIT() asm volatile("cp.async.commit_group;" ::: "memory")

__device__ __forceinline__ void ldsm_x4(uint32_t addr, uint32_t& r0, uint32_t& r1,
                                        uint32_t& r2, uint32_t& r3) {
    asm volatile("ldmatrix.sync.aligned.m8n8.x4.shared.b16 {%0,%1,%2,%3}, [%4];"
        : "=r"(r0), "=r"(r1), "=r"(r2), "=r"(r3) : "r"(addr));
}
__device__ __forceinline__ void mma_fp16(float* d, const uint32_t* a, uint32_t b0, uint32_t b1) {
    asm volatile(
        "mma.sync.aligned.m16n8k16.row.col.f32.f16.f16.f32 "
        "{%0,%1,%2,%3}, {%4,%5,%6,%7}, {%8,%9}, {%0,%1,%2,%3};"
        : "+f"(d[0]), "+f"(d[1]), "+f"(d[2]), "+f"(d[3])
        : "r"(a[0]), "r"(a[1]), "r"(a[2]), "r"(a[3]), "r"(b0), "r"(b1));
}

// ---------------------------------------------------------------------------
// Conversion kernels
// ---------------------------------------------------------------------------
__global__ __launch_bounds__(256)
void tohalf_kernel(const float* __restrict__ in, __half* __restrict__ out, size_t n)
{
    size_t i = ((size_t)blockIdx.x * 256 + threadIdx.x) * 4;
    if (i >= n) return;
    float4 v = *reinterpret_cast<const float4*>(in + i);
    *reinterpret_cast<__half2*>(out + i)     = __floats2half2_rn(v.x, v.y);
    *reinterpret_cast<__half2*>(out + i + 2) = __floats2half2_rn(v.z, v.w);
}

// Transposed convert: out[c][r] = fp16(in[r][c]), per batch z. in: [R,C], out: [C,R].
__global__ __launch_bounds__(256)
void transpose_h(const float* __restrict__ in, __half* __restrict__ out, int R, int C)
{
    __shared__ float t[32][33];
    const size_t zoff = (size_t)blockIdx.z * R * C;
    const float* ib = in + zoff;
    const int r0 = blockIdx.y * 32, c0 = blockIdx.x * 32;
    const int tx = threadIdx.x, ty = threadIdx.y;   // 32 x 8
#pragma unroll
    for (int i = 0; i < 32; i += 8)
        t[ty + i][tx] = ib[(size_t)(r0 + ty + i) * C + c0 + tx];
    __syncthreads();
#pragma unroll
    for (int i = 0; i < 32; i += 8) {
        size_t o = zoff + (size_t)(c0 + ty + i) * R + r0 + tx;
        out[o] = __float2half_rn(t[tx][ty + i]);
    }
}

// ---------------------------------------------------------------------------
// mma.sync fp16 NT GEMM: D[m][n] = alpha * sum_k A[m][k]*B[n][k], fp32 accum.
//   BM=BN=128, BK=64 (128B rows, XOR swizzle), 3-stage cp.async pipeline
//   (32KB/stage, 96KB total).
//   8 warps = 4(m) x 2(n); warp tile 32x64; atoms m16n8k16.
//   EPI=0: fp32 out.  EPI=1: fp16 out.
// ---------------------------------------------------------------------------
#define GBM 128
#define GBN 128
#define GBK 64
#define NSTAGE 3
#define TILE_BYTES 16384                       // one 128x64 fp16 tile
#define STAGE_BYTES (2 * TILE_BYTES)           // A, B
#define GEMM_SMEM (NSTAGE * STAGE_BYTES)       // 98304

template <int EPI>
__global__ __launch_bounds__(256)
void gemm_nt_mma(int M, int N, int K, float alpha,
                 const __half* __restrict__ A, size_t sA,
                 const __half* __restrict__ B, size_t sB,
                 float* __restrict__ Cf, __half* __restrict__ Ch, size_t sC)
{
    extern __shared__ __align__(128) char sm[];
    const uint32_t smbase = smem_u32(sm);

    const int tid = threadIdx.x, lane = tid & 31, wid = tid >> 5;
    const int wm = wid & 3, wn = wid >> 2;            // 4 x 2 warp grid
    const int bm = blockIdx.y * GBM, bn = blockIdx.x * GBN;
    const size_t z = blockIdx.z;

    const int NIT = K / GBK;                          // 16 or 64; >= NSTAGE

    auto issue = [&](int it, int buf) {
        const __half* As = A + z * sA + (size_t)bm * K + it * GBK;
        const __half* Bs = B + z * sB + (size_t)bn * K + it * GBK;
        const uint32_t da = smbase + buf * STAGE_BYTES;
        const uint32_t db = da + TILE_BYTES;
#pragma unroll
        for (int i = 0; i < 4; i++) {
            int c   = tid + i * 256;
            int row = c >> 3;            // 0..127
            int ck  = c & 7;             // 16B chunk within 128B row
            uint32_t off = (uint32_t)(row * 128 + ((ck * 16) ^ ((row & 7) << 4)));
            cp16(da + off, As + (size_t)row * K + ck * 8);
            cp16(db + off, Bs + (size_t)row * K + ck * 8);
        }
        CP_COMMIT();
    };

    float d[2][8][4];
#pragma unroll
    for (int am = 0; am < 2; am++)
#pragma unroll
        for (int an = 0; an < 8; an++)
#pragma unroll
            for (int q = 0; q < 4; q++) d[am][an][q] = 0.0f;

    issue(0, 0);
    issue(1, 1);
    issue(2, 2);

    const int lrow = lane & 15;
    const int lcol = (lane >> 4) * 16;   // byte offset of 8-half group

    int buf = 0;
    for (int it = 0; it < NIT; it++) {
        // Retire the group that fills buffer `buf` (tail-aware wait count).
        if (it + 3 <= NIT)      asm volatile("cp.async.wait_group 2;" ::: "memory");
        else if (it + 2 == NIT) asm volatile("cp.async.wait_group 1;" ::: "memory");
        else                    asm volatile("cp.async.wait_group 0;" ::: "memory");
        __syncthreads();

        const uint32_t Aa = smbase + buf * STAGE_BYTES;
        const uint32_t Ba = Aa + TILE_BYTES;

#pragma unroll
        for (int kk = 0; kk < 4; kk++) {
            const int colb = kk * 32 + lcol;
            uint32_t a[2][4], b[4][4];
#pragma unroll
            for (int am = 0; am < 2; am++) {
                int row = wm * 32 + am * 16 + lrow;
                uint32_t off = (uint32_t)(row * 128 + (colb ^ ((row & 7) << 4)));
                ldsm_x4(Aa + off, a[am][0], a[am][1], a[am][2], a[am][3]);
            }
#pragma unroll
            for (int nb = 0; nb < 4; nb++) {
                int row = wn * 64 + nb * 16 + lrow;
                uint32_t off = (uint32_t)(row * 128 + (colb ^ ((row & 7) << 4)));
                ldsm_x4(Ba + off, b[nb][0], b[nb][1], b[nb][2], b[nb][3]);
            }
#pragma unroll
            for (int am = 0; am < 2; am++)
#pragma unroll
                for (int an = 0; an < 8; an++)
                    mma_fp16(d[am][an], a[am], b[an >> 1][an & 1], b[an >> 1][(an & 1) + 2]);
        }
        __syncthreads();
        if (it + NSTAGE < NIT) issue(it + NSTAGE, buf);
        buf = (buf == NSTAGE - 1) ? 0 : buf + 1;
    }

    // Epilogue: per-atom store. c0,c1 at (row, col..col+1); c2,c3 at (row+8, ...).
    const int er = lane >> 2;
    const int ec = (lane & 3) * 2;
#pragma unroll
    for (int am = 0; am < 2; am++) {
#pragma unroll
        for (int an = 0; an < 8; an++) {
            const int row = bm + wm * 32 + am * 16 + er;
            const int col = bn + wn * 64 + an * 8 + ec;
            const float v0 = d[am][an][0] * alpha;
            const float v1 = d[am][an][1] * alpha;
            const float v2 = d[am][an][2] * alpha;
            const float v3 = d[am][an][3] * alpha;
            const size_t o0 = z * sC + (size_t)row * N + col;
            const size_t o1 = z * sC + (size_t)(row + 8) * N + col;
            if (EPI == 0) {
                *reinterpret_cast<float2*>(Cf + o0) = make_float2(v0, v1);
                *reinterpret_cast<float2*>(Cf + o1) = make_float2(v2, v3);
            } else {
                *reinterpret_cast<__half2*>(Ch + o0) = __floats2half2_rn(v0, v1);
                *reinterpret_cast<__half2*>(Ch + o1) = __floats2half2_rn(v2, v3);
            }
        }
    }
}

// ---------------------------------------------------------------------------
// Row softmax over SEQ=4096: reads fp32 S, writes fp16 P
// ---------------------------------------------------------------------------
__global__ __launch_bounds__(256)
void softmax_h_kernel(const float* __restrict__ S, __half* __restrict__ Ph)
{
    __shared__ float red[8];
    const size_t row = blockIdx.x;
    const float* p = S + row * (size_t)SEQ;
    const int tid = threadIdx.x, lane = tid & 31, warp = tid >> 5;

    float4 v[4];
    float m = -INFINITY;
#pragma unroll
    for (int i = 0; i < 4; i++) {
        v[i] = *reinterpret_cast<const float4*>(p + (size_t)(i * 256 + tid) * 4);
        m = fmaxf(m, fmaxf(fmaxf(v[i].x, v[i].y), fmaxf(v[i].z, v[i].w)));
    }
#pragma unroll
    for (int o = 16; o > 0; o >>= 1) m = fmaxf(m, __shfl_xor_sync(0xffffffffu, m, o));
    if (lane == 0) red[warp] = m;
    __syncthreads();
    if (warp == 0) {
        float t = red[lane & 7];
#pragma unroll
        for (int o = 4; o > 0; o >>= 1) t = fmaxf(t, __shfl_xor_sync(0xffffffffu, t, o));
        if (lane == 0) red[0] = t;
    }
    __syncthreads();
    m = red[0];
    __syncthreads();

    float s = 0.0f;
#pragma unroll
    for (int i = 0; i < 4; i++) {
        v[i].x = __expf(v[i].x - m);
        v[i].y = __expf(v[i].y - m);
        v[i].z = __expf(v[i].z - m);
        v[i].w = __expf(v[i].w - m);
        s += (v[i].x + v[i].y) + (v[i].z + v[i].w);
    }
#pragma unroll
    for (int o = 16; o > 0; o >>= 1) s += __shfl_xor_sync(0xffffffffu, s, o);
    if (lane == 0) red[warp] = s;
    __syncthreads();
    if (warp == 0) {
        float t = red[lane & 7];
#pragma unroll
        for (int o = 4; o > 0; o >>= 1) t += __shfl_xor_sync(0xffffffffu, t, o);
        if (lane == 0) red[0] = t;
    }
    __syncthreads();
    const float inv = 1.0f / red[0];

    const size_t rb = row * (size_t)SEQ;
#pragma unroll
    for (int i = 0; i < 4; i++) {
        size_t idx = rb + (size_t)(i * 256 + tid) * 4;
        *reinterpret_cast<__half2*>(Ph + idx)     = __floats2half2_rn(v[i].x * inv, v[i].y * inv);
        *reinterpret_cast<__half2*>(Ph + idx + 2) = __floats2half2_rn(v[i].z * inv, v[i].w * inv);
    }
}

// ---------------------------------------------------------------------------
extern "C" void kernel_launch(void* const* d_in, const int* in_sizes, int n_in,
                              void* d_out, int out_size)
{
    const float* x  = (const float*)d_in[0];   // [B, T, D]
    const float* QK = (const float*)d_in[1];   // [D, D]
    const float* VO = (const float*)d_in[2];   // [D, D]
    float* out = (float*)d_out;                // [B, T, D]

    float* S;
    __half *xh, *xth, *qkt, *vot, *xqk, *P, *av;
    cudaGetSymbolAddress((void**)&S,   g_S);
    cudaGetSymbolAddress((void**)&xh,  g_xh);
    cudaGetSymbolAddress((void**)&xth, g_xth);
    cudaGetSymbolAddress((void**)&qkt, g_QKt);
    cudaGetSymbolAddress((void**)&vot, g_VOt);
    cudaGetSymbolAddress((void**)&xqk, g_xqk);
    cudaGetSymbolAddress((void**)&P,   g_P);
    cudaGetSymbolAddress((void**)&av,  g_av);

    cudaFuncSetAttribute(gemm_nt_mma<0>, cudaFuncAttributeMaxDynamicSharedMemorySize, GEMM_SMEM);
    cudaFuncSetAttribute(gemm_nt_mma<1>, cudaFuncAttributeMaxDynamicSharedMemorySize, GEMM_SMEM);

    const size_t nx = (size_t)BATCH * SEQ * D_MODEL;   // 16M
    const size_t TD = (size_t)SEQ * D_MODEL;
    const size_t DT = (size_t)D_MODEL * SEQ;
    const size_t TT = (size_t)SEQ * SEQ;
    const float scale = 1.0f / 32.0f;                  // 1/sqrt(1024)

    // ---- conversions ----
    tohalf_kernel<<<(unsigned)(nx / 1024), 256>>>(x, xh, nx);
    transpose_h<<<dim3(D_MODEL / 32, D_MODEL / 32, 1), dim3(32, 8)>>>(QK, qkt, D_MODEL, D_MODEL);
    transpose_h<<<dim3(D_MODEL / 32, D_MODEL / 32, 1), dim3(32, 8)>>>(VO, vot, D_MODEL, D_MODEL);
    transpose_h<<<dim3(D_MODEL / 32, SEQ / 32, BATCH), dim3(32, 8)>>>(x, xth, SEQ, D_MODEL);

    // ---- 1) xQK = x . QK^T -> fp16
    gemm_nt_mma<1><<<dim3(D_MODEL / GBN, (BATCH * SEQ) / GBM, 1), 256, GEMM_SMEM>>>(
        BATCH * SEQ, D_MODEL, D_MODEL, 1.0f,
        xh, 0, qkt, 0, nullptr, xqk, 0);

    // ---- 2) S = (xQK . x^T)/32 : per batch -> fp32
    gemm_nt_mma<0><<<dim3(SEQ / GBN, SEQ / GBM, BATCH), 256, GEMM_SMEM>>>(
        SEQ, SEQ, D_MODEL, scale,
        xqk, TD, xh, TD, S, nullptr, TT);

    // ---- 3) P = softmax(S) -> fp16
    softmax_h_kernel<<<BATCH * SEQ, 256>>>(S, P);

    // ---- 4) av = P . (x^T)^T : per batch -> fp16
    gemm_nt_mma<1><<<dim3(D_MODEL / GBN, SEQ / GBM, BATCH), 256, GEMM_SMEM>>>(
        SEQ, D_MODEL, SEQ, 1.0f,
        P, TT, xth, DT, nullptr, av, TD);

    // ---- 5) out = av . VO^T -> fp32
    gemm_nt_mma<0><<<dim3(D_MODEL / GBN, (BATCH * SEQ) / GBM, 1), 256, GEMM_SMEM>>>(
        BATCH * SEQ, D_MODEL, D_MODEL, 1.0f,
        av, 0, vot, 0, out, nullptr, TD);
}

// round 12
// speedup vs baseline: 2.8692x; 1.0177x over previous
#include <cuda_runtime.h>
#include <cuda_fp16.h>
#include <math.h>
#include <stdint.h>

#define D_MODEL 1024
#define BATCH   4
#define SEQ     4096

// ---------------------------------------------------------------------------
// Scratch (__device__ globals: allocation-free rule)
// ---------------------------------------------------------------------------
__device__ __align__(256) float  g_S   [(size_t)BATCH * SEQ * SEQ];             // 256 MB
__device__ __align__(256) __half g_xh  [(size_t)BATCH * SEQ * D_MODEL];         // x fp16
__device__ __align__(256) __half g_xth [(size_t)BATCH * D_MODEL * SEQ];         // x^T fp16
__device__ __align__(256) __half g_QKt [(size_t)D_MODEL * D_MODEL];             // QK^T fp16
__device__ __align__(256) __half g_VOt [(size_t)D_MODEL * D_MODEL];             // VO^T fp16
__device__ __align__(256) __half g_xqk [(size_t)BATCH * SEQ * D_MODEL];
__device__ __align__(256) __half g_P   [(size_t)BATCH * SEQ * SEQ];             // 128 MB
__device__ __align__(256) __half g_av  [(size_t)BATCH * SEQ * D_MODEL];

// ---------------------------------------------------------------------------
// Helpers
// ---------------------------------------------------------------------------
__device__ __forceinline__ uint32_t smem_u32(const void* p) {
    uint32_t a;
    asm("{ .reg .u64 t; cvta.to.shared.u64 t, %1; cvt.u32.u64 %0, t; }" : "=r"(a) : "l"(p));
    return a;
}
__device__ __forceinline__ void cp16(uint32_t dst, const void* src) {
    asm volatile("cp.async.cg.shared.global [%0], [%1], 16;"
        :: "r"(dst), "l"(__cvta_generic_to_global(src)) : "memory");
}
#define CP_COMMIT() asm volatile("cp.async.commit_group;" ::: "memory")

__device__ __forceinline__ void ldsm_x4(uint32_t addr, uint32_t& r0, uint32_t& r1,
                                        uint32_t& r2, uint32_t& r3) {
    asm volatile("ldmatrix.sync.aligned.m8n8.x4.shared.b16 {%0,%1,%2,%3}, [%4];"
        : "=r"(r0), "=r"(r1), "=r"(r2), "=r"(r3) : "r"(addr));
}
__device__ __forceinline__ void mma_fp16(float* d, const uint32_t* a, uint32_t b0, uint32_t b1) {
    asm volatile(
        "mma.sync.aligned.m16n8k16.row.col.f32.f16.f16.f32 "
        "{%0,%1,%2,%3}, {%4,%5,%6,%7}, {%8,%9}, {%0,%1,%2,%3};"
        : "+f"(d[0]), "+f"(d[1]), "+f"(d[2]), "+f"(d[3])
        : "r"(a[0]), "r"(a[1]), "r"(a[2]), "r"(a[3]), "r"(b0), "r"(b1));
}

// ---------------------------------------------------------------------------
// Conversion kernels
// ---------------------------------------------------------------------------
// Transposed convert: out[c][r] = fp16(in[r][c]), per batch z. in: [R,C], out: [C,R].
__global__ __launch_bounds__(256)
void transpose_h(const float* __restrict__ in, __half* __restrict__ out, int R, int C)
{
    __shared__ float t[32][33];
    const size_t zoff = (size_t)blockIdx.z * R * C;
    const float* ib = in + zoff;
    const int r0 = blockIdx.y * 32, c0 = blockIdx.x * 32;
    const int tx = threadIdx.x, ty = threadIdx.y;   // 32 x 8
#pragma unroll
    for (int i = 0; i < 32; i += 8)
        t[ty + i][tx] = ib[(size_t)(r0 + ty + i) * C + c0 + tx];
    __syncthreads();
#pragma unroll
    for (int i = 0; i < 32; i += 8) {
        size_t o = zoff + (size_t)(c0 + ty + i) * R + r0 + tx;
        out[o] = __float2half_rn(t[tx][ty + i]);
    }
}

// Dual convert: outn = fp16(in) (same layout) AND outt = fp16(in^T). One read of x.
__global__ __launch_bounds__(256)
void transpose_dual_h(const float* __restrict__ in, __half* __restrict__ outn,
                      __half* __restrict__ outt, int R, int C)
{
    __shared__ float t[32][33];
    const size_t zoff = (size_t)blockIdx.z * R * C;
    const float* ib = in + zoff;
    const int r0 = blockIdx.y * 32, c0 = blockIdx.x * 32;
    const int tx = threadIdx.x, ty = threadIdx.y;   // 32 x 8
#pragma unroll
    for (int i = 0; i < 32; i += 8) {
        float v = ib[(size_t)(r0 + ty + i) * C + c0 + tx];
        t[ty + i][tx] = v;
        outn[zoff + (size_t)(r0 + ty + i) * C + c0 + tx] = __float2half_rn(v);
    }
    __syncthreads();
#pragma unroll
    for (int i = 0; i < 32; i += 8) {
        size_t o = zoff + (size_t)(c0 + ty + i) * R + r0 + tx;
        outt[o] = __float2half_rn(t[tx][ty + i]);
    }
}

// ---------------------------------------------------------------------------
// mma.sync fp16 NT GEMM: D[m][n] = alpha * sum_k A[m][k]*B[n][k], fp32 accum.
//   BM=BN=128, BK=64 (128B rows, XOR swizzle), 2-stage cp.async pipeline
//   (32KB/stage, 64KB total) -> 2 CTAs/SM via __launch_bounds__(256, 2).
//   8 warps = 4(m) x 2(n); warp tile 32x64; atoms m16n8k16.
//   EPI=0: fp32 out.  EPI=1: fp16 out.
// ---------------------------------------------------------------------------
#define GBM 128
#define GBN 128
#define GBK 64
#define NSTAGE 2
#define TILE_BYTES 16384                       // one 128x64 fp16 tile
#define STAGE_BYTES (2 * TILE_BYTES)           // A, B
#define GEMM_SMEM (NSTAGE * STAGE_BYTES)       // 65536

template <int EPI>
__global__ __launch_bounds__(256, 2)
void gemm_nt_mma(int M, int N, int K, float alpha,
                 const __half* __restrict__ A, size_t sA,
                 const __half* __restrict__ B, size_t sB,
                 float* __restrict__ Cf, __half* __restrict__ Ch, size_t sC)
{
    extern __shared__ __align__(128) char sm[];
    const uint32_t smbase = smem_u32(sm);

    const int tid = threadIdx.x, lane = tid & 31, wid = tid >> 5;
    const int wm = wid & 3, wn = wid >> 2;            // 4 x 2 warp grid
    const int bm = blockIdx.y * GBM, bn = blockIdx.x * GBN;
    const size_t z = blockIdx.z;

    const int NIT = K / GBK;                          // 16 or 64; >= NSTAGE

    auto issue = [&](int it, int buf) {
        const __half* As = A + z * sA + (size_t)bm * K + it * GBK;
        const __half* Bs = B + z * sB + (size_t)bn * K + it * GBK;
        const uint32_t da = smbase + buf * STAGE_BYTES;
        const uint32_t db = da + TILE_BYTES;
#pragma unroll
        for (int i = 0; i < 4; i++) {
            int c   = tid + i * 256;
            int row = c >> 3;            // 0..127
            int ck  = c & 7;             // 16B chunk within 128B row
            uint32_t off = (uint32_t)(row * 128 + ((ck * 16) ^ ((row & 7) << 4)));
            cp16(da + off, As + (size_t)row * K + ck * 8);
            cp16(db + off, Bs + (size_t)row * K + ck * 8);
        }
        CP_COMMIT();
    };

    float d[2][8][4];
#pragma unroll
    for (int am = 0; am < 2; am++)
#pragma unroll
        for (int an = 0; an < 8; an++)
#pragma unroll
            for (int q = 0; q < 4; q++) d[am][an][q] = 0.0f;

    issue(0, 0);
    issue(1, 1);

    const int lrow = lane & 15;
    const int lcol = (lane >> 4) * 16;   // byte offset of 8-half group

    for (int it = 0; it < NIT; it++) {
        // Retire the group that fills buffer `it & 1` (tail-aware wait count).
        if (it + 1 < NIT) asm volatile("cp.async.wait_group 1;" ::: "memory");
        else              asm volatile("cp.async.wait_group 0;" ::: "memory");
        __syncthreads();

        const int buf = it & 1;
        const uint32_t Aa = smbase + buf * STAGE_BYTES;
        const uint32_t Ba = Aa + TILE_BYTES;

#pragma unroll
        for (int kk = 0; kk < 4; kk++) {
            const int colb = kk * 32 + lcol;
            uint32_t a[2][4], b[4][4];
#pragma unroll
            for (int am = 0; am < 2; am++) {
                int row = wm * 32 + am * 16 + lrow;
                uint32_t off = (uint32_t)(row * 128 + (colb ^ ((row & 7) << 4)));
                ldsm_x4(Aa + off, a[am][0], a[am][1], a[am][2], a[am][3]);
            }
#pragma unroll
            for (int nb = 0; nb < 4; nb++) {
                int row = wn * 64 + nb * 16 + lrow;
                uint32_t off = (uint32_t)(row * 128 + (colb ^ ((row & 7) << 4)));
                ldsm_x4(Ba + off, b[nb][0], b[nb][1], b[nb][2], b[nb][3]);
            }
#pragma unroll
            for (int am = 0; am < 2; am++)
#pragma unroll
                for (int an = 0; an < 8; an++)
                    mma_fp16(d[am][an], a[am], b[an >> 1][an & 1], b[an >> 1][(an & 1) + 2]);
        }
        __syncthreads();
        if (it + NSTAGE < NIT) issue(it + NSTAGE, buf);
    }

    // Epilogue: per-atom store. c0,c1 at (row, col..col+1); c2,c3 at (row+8, ...).
    const int er = lane >> 2;
    const int ec = (lane & 3) * 2;
#pragma unroll
    for (int am = 0; am < 2; am++) {
#pragma unroll
        for (int an = 0; an < 8; an++) {
            const int row = bm + wm * 32 + am * 16 + er;
            const int col = bn + wn * 64 + an * 8 + ec;
            const float v0 = d[am][an][0] * alpha;
            const float v1 = d[am][an][1] * alpha;
            const float v2 = d[am][an][2] * alpha;
            const float v3 = d[am][an][3] * alpha;
            const size_t o0 = z * sC + (size_t)row * N + col;
            const size_t o1 = z * sC + (size_t)(row + 8) * N + col;
            if (EPI == 0) {
                *reinterpret_cast<float2*>(Cf + o0) = make_float2(v0, v1);
                *reinterpret_cast<float2*>(Cf + o1) = make_float2(v2, v3);
            } else {
                *reinterpret_cast<__half2*>(Ch + o0) = __floats2half2_rn(v0, v1);
                *reinterpret_cast<__half2*>(Ch + o1) = __floats2half2_rn(v2, v3);
            }
        }
    }
}

// ---------------------------------------------------------------------------
// Row softmax over SEQ=4096: reads fp32 S, writes fp16 P
// ---------------------------------------------------------------------------
__global__ __launch_bounds__(256)
void softmax_h_kernel(const float* __restrict__ S, __half* __restrict__ Ph)
{
    __shared__ float red[8];
    const size_t row = blockIdx.x;
    const float* p = S + row * (size_t)SEQ;
    const int tid = threadIdx.x, lane = tid & 31, warp = tid >> 5;

    float4 v[4];
    float m = -INFINITY;
#pragma unroll
    for (int i = 0; i < 4; i++) {
        v[i] = *reinterpret_cast<const float4*>(p + (size_t)(i * 256 + tid) * 4);
        m = fmaxf(m, fmaxf(fmaxf(v[i].x, v[i].y), fmaxf(v[i].z, v[i].w)));
    }
#pragma unroll
    for (int o = 16; o > 0; o >>= 1) m = fmaxf(m, __shfl_xor_sync(0xffffffffu, m, o));
    if (lane == 0) red[warp] = m;
    __syncthreads();
    if (warp == 0) {
        float t = red[lane & 7];
#pragma unroll
        for (int o = 4; o > 0; o >>= 1) t = fmaxf(t, __shfl_xor_sync(0xffffffffu, t, o));
        if (lane == 0) red[0] = t;
    }
    __syncthreads();
    m = red[0];
    __syncthreads();

    float s = 0.0f;
#pragma unroll
    for (int i = 0; i < 4; i++) {
        v[i].x = __expf(v[i].x - m);
        v[i].y = __expf(v[i].y - m);
        v[i].z = __expf(v[i].z - m);
        v[i].w = __expf(v[i].w - m);
        s += (v[i].x + v[i].y) + (v[i].z + v[i].w);
    }
#pragma unroll
    for (int o = 16; o > 0; o >>= 1) s += __shfl_xor_sync(0xffffffffu, s, o);
    if (lane == 0) red[warp] = s;
    __syncthreads();
    if (warp == 0) {
        float t = red[lane & 7];
#pragma unroll
        for (int o = 4; o > 0; o >>= 1) t += __shfl_xor_sync(0xffffffffu, t, o);
        if (lane == 0) red[0] = t;
    }
    __syncthreads();
    const float inv = 1.0f / red[0];

    const size_t rb = row * (size_t)SEQ;
#pragma unroll
    for (int i = 0; i < 4; i++) {
        size_t idx = rb + (size_t)(i * 256 + tid) * 4;
        *reinterpret_cast<__half2*>(Ph + idx)     = __floats2half2_rn(v[i].x * inv, v[i].y * inv);
        *reinterpret_cast<__half2*>(Ph + idx + 2) = __floats2half2_rn(v[i].z * inv, v[i].w * inv);
    }
}

// ---------------------------------------------------------------------------
extern "C" void kernel_launch(void* const* d_in, const int* in_sizes, int n_in,
                              void* d_out, int out_size)
{
    const float* x  = (const float*)d_in[0];   // [B, T, D]
    const float* QK = (const float*)d_in[1];   // [D, D]
    const float* VO = (const float*)d_in[2];   // [D, D]
    float* out = (float*)d_out;                // [B, T, D]

    float* S;
    __half *xh, *xth, *qkt, *vot, *xqk, *P, *av;
    cudaGetSymbolAddress((void**)&S,   g_S);
    cudaGetSymbolAddress((void**)&xh,  g_xh);
    cudaGetSymbolAddress((void**)&xth, g_xth);
    cudaGetSymbolAddress((void**)&qkt, g_QKt);
    cudaGetSymbolAddress((void**)&vot, g_VOt);
    cudaGetSymbolAddress((void**)&xqk, g_xqk);
    cudaGetSymbolAddress((void**)&P,   g_P);
    cudaGetSymbolAddress((void**)&av,  g_av);

    cudaFuncSetAttribute(gemm_nt_mma<0>, cudaFuncAttributeMaxDynamicSharedMemorySize, GEMM_SMEM);
    cudaFuncSetAttribute(gemm_nt_mma<1>, cudaFuncAttributeMaxDynamicSharedMemorySize, GEMM_SMEM);

    const size_t TD = (size_t)SEQ * D_MODEL;
    const size_t DT = (size_t)D_MODEL * SEQ;
    const size_t TT = (size_t)SEQ * SEQ;
    const float scale = 1.0f / 32.0f;                  // 1/sqrt(1024)

    // ---- conversions ----
    transpose_h<<<dim3(D_MODEL / 32, D_MODEL / 32, 1), dim3(32, 8)>>>(QK, qkt, D_MODEL, D_MODEL);
    transpose_h<<<dim3(D_MODEL / 32, D_MODEL / 32, 1), dim3(32, 8)>>>(VO, vot, D_MODEL, D_MODEL);
    transpose_dual_h<<<dim3(D_MODEL / 32, SEQ / 32, BATCH), dim3(32, 8)>>>(x, xh, xth, SEQ, D_MODEL);

    // ---- 1) xQK = x . QK^T -> fp16
    gemm_nt_mma<1><<<dim3(D_MODEL / GBN, (BATCH * SEQ) / GBM, 1), 256, GEMM_SMEM>>>(
        BATCH * SEQ, D_MODEL, D_MODEL, 1.0f,
        xh, 0, qkt, 0, nullptr, xqk, 0);

    // ---- 2) S = (xQK . x^T)/32 : per batch -> fp32
    gemm_nt_mma<0><<<dim3(SEQ / GBN, SEQ / GBM, BATCH), 256, GEMM_SMEM>>>(
        SEQ, SEQ, D_MODEL, scale,
        xqk, TD, xh, TD, S, nullptr, TT);

    // ---- 3) P = softmax(S) -> fp16
    softmax_h_kernel<<<BATCH * SEQ, 256>>>(S, P);

    // ---- 4) av = P . (x^T)^T : per batch -> fp16
    gemm_nt_mma<1><<<dim3(D_MODEL / GBN, SEQ / GBM, BATCH), 256, GEMM_SMEM>>>(
        SEQ, D_MODEL, SEQ, 1.0f,
        P, TT, xth, DT, nullptr, av, TD);

    // ---- 5) out = av . VO^T -> fp32
    gemm_nt_mma<0><<<dim3(D_MODEL / GBN, (BATCH * SEQ) / GBM, 1), 256, GEMM_SMEM>>>(
        BATCH * SEQ, D_MODEL, D_MODEL, 1.0f,
        av, 0, vot, 0, out, nullptr, TD);
}